// round 4
// baseline (speedup 1.0000x reference)
#include <cuda_runtime.h>
#include <math.h>

#define Bn   32
#define Cn   256
#define Hn   64
#define Wn   64
#define HWn  4096
#define AUXn 64
#define RANKn 64
#define HIDn 256
#define OSn  8
#define PI_F 3.14159265358979323846f

// ---------------- scratch (static device globals; no allocs) ----------------
__device__ __align__(128) float d_gpart[Bn * 16 * Cn];   // per-(b,tile,c) spatial-sum partials
__device__ __align__(128) float d_av[Bn * HWn];          // channel mean
__device__ __align__(128) float d_mx[Bn * HWn];          // channel max
__device__ __align__(128) float d_h[Bn * HIDn];          // hidden activations
__device__ __align__(128) float d_phic[Bn * RANKn];      // phi_c
__device__ __align__(128) float d_pco[Bn * 10];          // stencil coeffs
__device__ __align__(128) float d_Ep[Bn * 9 * Cn];       // [b][ks][c] einsum partials (ks=8: bias)
__device__ __align__(128) float d_Mp[Bn * 8 * Cn];       // [b][kc][c] m_base_c partials

// ---------------- K1: fused stats pass over x ----------------
// grid (16 tiles of 256 positions, Bn), 256 threads (8 warps).
// Warp w owns channels [w*32, w*32+32); lanes cover 256 positions as 2x LDG.128.
__global__ void k1_stats(const float* __restrict__ x) {
    const int b    = blockIdx.y;
    const int tile = blockIdx.x;
    const int t    = threadIdx.x;
    const int warp = t >> 5, lane = t & 31;
    const int pos0 = tile * 256;

    __shared__ float avp[8][256];
    __shared__ float mxp[8][256];

    const float4* xb = (const float4*)(x + (size_t)b * Cn * HWn);
    const int p4base = (pos0 >> 2) + lane;

    float4 av0 = {0,0,0,0}, av1 = {0,0,0,0};
    const float NI = -3.402823466e38f;
    float4 mx0 = {NI,NI,NI,NI}, mx1 = mx0;

    const int cbase = warp * 32;
    #pragma unroll 4
    for (int cc = 0; cc < 32; cc++) {
        const int c = cbase + cc;
        const size_t row = (size_t)c * (HWn / 4) + p4base;
        float4 v0 = __ldg(&xb[row]);
        float4 v1 = __ldg(&xb[row + 32]);

        av0.x += v0.x; av0.y += v0.y; av0.z += v0.z; av0.w += v0.w;
        av1.x += v1.x; av1.y += v1.y; av1.z += v1.z; av1.w += v1.w;
        mx0.x = fmaxf(mx0.x, v0.x); mx0.y = fmaxf(mx0.y, v0.y); mx0.z = fmaxf(mx0.z, v0.z); mx0.w = fmaxf(mx0.w, v0.w);
        mx1.x = fmaxf(mx1.x, v1.x); mx1.y = fmaxf(mx1.y, v1.y); mx1.z = fmaxf(mx1.z, v1.z); mx1.w = fmaxf(mx1.w, v1.w);

        float r = ((v0.x + v0.y) + (v0.z + v0.w)) + ((v1.x + v1.y) + (v1.z + v1.w));
        #pragma unroll
        for (int o = 16; o; o >>= 1) r += __shfl_xor_sync(0xffffffffu, r, o);
        if (lane == 0) d_gpart[(b * 16 + tile) * Cn + c] = r;
    }

    *(float4*)&avp[warp][lane * 4]       = av0;
    *(float4*)&avp[warp][128 + lane * 4] = av1;
    *(float4*)&mxp[warp][lane * 4]       = mx0;
    *(float4*)&mxp[warp][128 + lane * 4] = mx1;
    __syncthreads();

    {
        const int p = t;
        float s = 0.f, m = NI;
        #pragma unroll
        for (int w = 0; w < 8; w++) { s += avp[w][p]; m = fmaxf(m, mxp[w][p]); }
        d_av[b * HWn + pos0 + p] = s * (1.f / (float)Cn);
        d_mx[b * HWn + pos0 + p] = m;
    }
}

// ---------------- K2: per-batch MLP head (h, phi_c/phi_s, m_base_s, s_m -> pco) ----------------
__global__ void k2_mlp(const float* __restrict__ a,
                       const float* __restrict__ W_pre, const float* __restrict__ b_pre,
                       const float* __restrict__ W_bs,  const float* __restrict__ b_bs,
                       const float* __restrict__ W_pc,  const float* __restrict__ b_pc,
                       const float* __restrict__ W_ps,  const float* __restrict__ b_ps,
                       const float* __restrict__ W_Ws,  const float* __restrict__ b_Ws) {
    const int b = blockIdx.x;
    const int t = threadIdx.x;

    __shared__ float in_s[Cn + AUXn];
    __shared__ float h_s[HIDn];
    __shared__ float phis_s[RANKn];
    __shared__ float mbs_s[OSn], sm_s[OSn];
    __shared__ float sred[OSn * RANKn];

    {
        float g = 0.f;
        #pragma unroll
        for (int tl = 0; tl < 16; tl++) g += d_gpart[(b * 16 + tl) * Cn + t];
        in_s[t] = g * (1.f / (float)HWn);
        if (t < AUXn) in_s[Cn + t] = __ldg(a + b * AUXn + t);
    }
    __syncthreads();

    // h = relu(in @ W_pre + b_pre), dual accumulators
    {
        float a0 = __ldg(b_pre + t), a1 = 0.f;
        #pragma unroll 4
        for (int i = 0; i < Cn + AUXn; i += 2) {
            a0 = fmaf(in_s[i],     __ldg(W_pre + i * HIDn + t), a0);
            a1 = fmaf(in_s[i + 1], __ldg(W_pre + (i + 1) * HIDn + t), a1);
        }
        float h = fmaxf(a0 + a1, 0.f);
        h_s[t] = h;
        d_h[b * HIDn + t] = h;
    }
    __syncthreads();

    if (t < 32) {
        float p = __ldg(b_pc + t);
        #pragma unroll 4
        for (int k = 0; k < HIDn; k++)
            p = fmaf(h_s[k], __ldg(W_pc + k * RANKn + t), p);
        float w = 1.f + (PI_F - 1.f) * (float)t / 31.f;
        float u = p * w;
        d_phic[b * RANKn + t]      = sinf(u);
        d_phic[b * RANKn + t + 32] = cosf(u);
    } else if (t < 64) {
        int r = t - 32;
        float p = __ldg(b_ps + r);
        #pragma unroll 4
        for (int k = 0; k < HIDn; k++)
            p = fmaf(h_s[k], __ldg(W_ps + k * RANKn + r), p);
        float w = 1.f + (PI_F - 1.f) * (float)r / 31.f;
        float u = p * w;
        phis_s[r]      = sinf(u);
        phis_s[r + 32] = cosf(u);
    } else if (t < 64 + OSn) {
        int s = t - 64;
        float mbs = __ldg(b_bs + s);
        for (int k = 0; k < HIDn; k++)
            mbs = fmaf(h_s[k], __ldg(W_bs + k * OSn + s), mbs);
        mbs_s[s] = mbs;
    }
    __syncthreads();

    #pragma unroll
    for (int o = t; o < OSn * RANKn; o += 256) {
        int r = o & 63;
        float a0 = __ldg(b_Ws + o), a1 = 0.f;
        #pragma unroll 4
        for (int k = 0; k < HIDn; k += 2) {
            a0 = fmaf(h_s[k],     __ldg(W_Ws + k * (OSn * RANKn) + o), a0);
            a1 = fmaf(h_s[k + 1], __ldg(W_Ws + (k + 1) * (OSn * RANKn) + o), a1);
        }
        sred[o] = (a0 + a1) * phis_s[r];
    }
    __syncthreads();

    if (t < OSn) {
        float sm = 0.f;
        #pragma unroll
        for (int r = 0; r < RANKn; r++) sm += sred[t * RANKn + r];
        sm_s[t] = mbs_s[t] * sm;
    }
    __syncthreads();

    if (t < OSn) {
        d_pco[b * 10 + (t >> 2) * 5 + (t & 3)] = sm_s[t];
    } else if (t < OSn + 2) {
        int j = t - OSn;
        float cc = -(sm_s[j * 4] + sm_s[j * 4 + 1] + sm_s[j * 4 + 2] + sm_s[j * 4 + 3]);
        d_pco[b * 10 + j * 5 + 4] = cc;
    }
}

// ---------------- K3: broadcast-pattern per-channel contractions ----------------
// grid (32 c-tiles, 17 splits), 256 threads. lane = b, warp = c within tile.
//  ks in [0,8): Ep partial = sum_{k in chunk, r} h[b,k] phi[b,r] W_Wc[k, c*64+r]
//  ks == 8   : Ep bias    = sum_r phi[b,r] b_Wc[c*64+r]
//  ks in [9,17): Mp partial = sum_{k in chunk} h[b,k] W_bc[k, c]
// W matrices are read (near-)once chip-wide, broadcast across the 32 b-lanes.
__global__ void k3_einsum(const float* __restrict__ W_Wc, const float* __restrict__ b_Wc,
                          const float* __restrict__ W_bc) {
    const int ct = blockIdx.x;
    const int ks = blockIdx.y;
    const int t  = threadIdx.x;
    const int lane = t & 31;     // = b
    const int warp = t >> 5;
    const int c = ct * 8 + warp;

    __shared__ float h_s[32 * 33];
    __shared__ float phi_s[32 * 68];

    if (ks != 8) {
        const int kc = (ks < 8) ? ks : (ks - 9);
        for (int i = t; i < 32 * 32; i += 256) {
            int bb = i >> 5, kk = i & 31;
            h_s[bb * 33 + kk] = d_h[bb * HIDn + kc * 32 + kk];
        }
    }
    if (ks <= 8) {
        for (int i = t; i < 32 * 64; i += 256) {
            int bb = i >> 6, r = i & 63;
            phi_s[bb * 68 + r] = d_phic[bb * RANKn + r];
        }
    }
    __syncthreads();

    if (ks < 8) {
        float acc = 0.f;
        const float* Wbase = W_Wc + (size_t)(ks * 32) * (Cn * RANKn) + c * RANKn;
        #pragma unroll 2
        for (int kk = 0; kk < 32; kk++) {
            float hk = h_s[lane * 33 + kk];
            const float4* w4 = (const float4*)(Wbase + (size_t)kk * (Cn * RANKn));
            float dot = 0.f;
            #pragma unroll
            for (int r4 = 0; r4 < 16; r4++) {
                float4 w = __ldg(&w4[r4]);   // broadcast across lanes
                float4 p = *(const float4*)(phi_s + lane * 68 + r4 * 4);
                dot = fmaf(w.x, p.x, dot);
                dot = fmaf(w.y, p.y, dot);
                dot = fmaf(w.z, p.z, dot);
                dot = fmaf(w.w, p.w, dot);
            }
            acc = fmaf(hk, dot, acc);
        }
        d_Ep[(lane * 9 + ks) * Cn + c] = acc;
    } else if (ks == 8) {
        float acc = 0.f;
        const float4* bw4 = (const float4*)(b_Wc + c * RANKn);
        #pragma unroll
        for (int r4 = 0; r4 < 16; r4++) {
            float4 w = __ldg(&bw4[r4]);
            float4 p = *(const float4*)(phi_s + lane * 68 + r4 * 4);
            acc = fmaf(w.x, p.x, acc);
            acc = fmaf(w.y, p.y, acc);
            acc = fmaf(w.z, p.z, acc);
            acc = fmaf(w.w, p.w, acc);
        }
        d_Ep[(lane * 9 + 8) * Cn + c] = acc;
    } else {
        const int kc = ks - 9;
        float a0 = 0.f, a1 = 0.f;
        const float* Wb = W_bc + (size_t)(kc * 32) * Cn + c;
        #pragma unroll 4
        for (int kk = 0; kk < 32; kk += 2) {
            a0 = fmaf(h_s[lane * 33 + kk],     __ldg(Wb + (size_t)kk * Cn), a0);
            a1 = fmaf(h_s[lane * 33 + kk + 1], __ldg(Wb + (size_t)(kk + 1) * Cn), a1);
        }
        d_Mp[(lane * 8 + kc) * Cn + c] = a0 + a1;
    }
}

// ---------------- K5: fused sig tables + output pass ----------------
// grid (4 hw4-tiles, Bn*8 c-groups), 256 threads.
// Warp 0 builds sigc for the block's 32 channels; every thread builds convsig
// for its own 4 positions (cheap 8x recompute across cg); then the 32-channel
// multiply loop streams x -> out.
__global__ void k5_out(const float* __restrict__ x, float* __restrict__ out,
                       const float* __restrict__ b_bc) {
    const int t   = threadIdx.x;
    const int hw4 = blockIdx.x * 256 + t;
    const int bcg = blockIdx.y;
    const int b   = bcg >> 3;
    const int cg  = bcg & 7;

    __shared__ float sig_s[32];
    __shared__ float pc_s[10];

    if (t < 32) {
        const int c = cg * 32 + t;
        float e = 0.f;
        #pragma unroll
        for (int ks = 0; ks < 9; ks++) e += d_Ep[(b * 9 + ks) * Cn + c];
        float m = __ldg(b_bc + c);
        #pragma unroll
        for (int kc = 0; kc < 8; kc++) m += d_Mp[(b * 8 + kc) * Cn + c];
        float cm = m * e;
        sig_s[t] = 1.f / (1.f + expf(-cm));
    } else if (t >= 32 && t < 42) {
        pc_s[t - 32] = d_pco[b * 10 + (t - 32)];
    }
    __syncthreads();

    // convsig for this thread's 4 positions
    const float* av = d_av + b * HWn;
    const float* mx = d_mx + b * HWn;
    float cvr[4];
    #pragma unroll
    for (int j = 0; j < 4; j++) {
        const int p  = hw4 * 4 + j;
        const int hh = p >> 6, ww = p & 63;
        float up_a = (hh > 0)      ? __ldg(av + p - Wn) : 0.f;
        float dn_a = (hh < Hn - 1) ? __ldg(av + p + Wn) : 0.f;
        float lf_a = (ww > 0)      ? __ldg(av + p - 1)  : 0.f;
        float rt_a = (ww < Wn - 1) ? __ldg(av + p + 1)  : 0.f;
        float ce_a = __ldg(av + p);
        float up_m = (hh > 0)      ? __ldg(mx + p - Wn) : 0.f;
        float dn_m = (hh < Hn - 1) ? __ldg(mx + p + Wn) : 0.f;
        float lf_m = (ww > 0)      ? __ldg(mx + p - 1)  : 0.f;
        float rt_m = (ww < Wn - 1) ? __ldg(mx + p + 1)  : 0.f;
        float ce_m = __ldg(mx + p);
        float conv = pc_s[0] * up_a + pc_s[1] * dn_a + pc_s[2] * lf_a + pc_s[3] * rt_a + pc_s[4] * ce_a
                   + pc_s[5] * up_m + pc_s[6] * dn_m + pc_s[7] * lf_m + pc_s[8] * rt_m + pc_s[9] * ce_m;
        cvr[j] = 1.f / (1.f + expf(-conv));
    }

    const size_t base = ((size_t)(b * Cn + cg * 32)) * (HWn / 4) + hw4;
    const float4* x4 = (const float4*)x;
    float4* o4 = (float4*)out;

    #pragma unroll 8
    for (int ci = 0; ci < 32; ci++) {
        float s = sig_s[ci] + 1.f;
        float4 v = __ldg(&x4[base + (size_t)ci * (HWn / 4)]);
        float4 o;
        o.x = v.x * (s + cvr[0]);
        o.y = v.y * (s + cvr[1]);
        o.z = v.z * (s + cvr[2]);
        o.w = v.w * (s + cvr[3]);
        o4[base + (size_t)ci * (HWn / 4)] = o;
    }
}

// ---------------- launch ----------------
extern "C" void kernel_launch(void* const* d_in, const int* in_sizes, int n_in,
                              void* d_out, int out_size) {
    (void)in_sizes; (void)n_in; (void)out_size;
    const float* x     = (const float*)d_in[0];
    const float* a     = (const float*)d_in[1];
    const float* W_pre = (const float*)d_in[2];
    const float* b_pre = (const float*)d_in[3];
    const float* W_bc  = (const float*)d_in[4];
    const float* b_bc  = (const float*)d_in[5];
    const float* W_bs  = (const float*)d_in[6];
    const float* b_bs  = (const float*)d_in[7];
    const float* W_pc  = (const float*)d_in[8];
    const float* b_pc  = (const float*)d_in[9];
    const float* W_ps  = (const float*)d_in[10];
    const float* b_ps  = (const float*)d_in[11];
    const float* W_Wc  = (const float*)d_in[12];
    const float* b_Wc  = (const float*)d_in[13];
    const float* W_Ws  = (const float*)d_in[14];
    const float* b_Ws  = (const float*)d_in[15];
    float* out = (float*)d_out;

    k1_stats <<<dim3(16, Bn), 256>>>(x);
    k2_mlp   <<<Bn, 256>>>(a, W_pre, b_pre, W_bs, b_bs,
                           W_pc, b_pc, W_ps, b_ps, W_Ws, b_Ws);
    k3_einsum<<<dim3(32, 17), 256>>>(W_Wc, b_Wc, W_bc);
    k5_out   <<<dim3(4, Bn * 8), 256>>>(x, out, b_bc);
}

// round 6
// speedup vs baseline: 1.5043x; 1.5043x over previous
#include <cuda_runtime.h>
#include <math.h>

#define Bn   32
#define Cn   256
#define Hn   64
#define Wn   64
#define HWn  4096
#define AUXn 64
#define RANKn 64
#define HIDn 256
#define OSn  8
#define PI_F 3.14159265358979323846f

// ---------------- scratch ----------------
__device__ __align__(128) float d_gpart[Bn * 8 * Cn];
__device__ __align__(128) float d_av[Bn * HWn];
__device__ __align__(128) float d_mx[Bn * HWn];
__device__ __align__(128) float d_h[Bn * HIDn];
__device__ __align__(128) float d_phic[Bn * RANKn];
__device__ __align__(128) float d_phis[Bn * RANKn];
__device__ __align__(128) float d_Ep[Bn * 9 * Cn];    // [b][ks][c] Wc-einsum partials (ks=8: bias)
__device__ __align__(128) float d_Mp[Bn * 8 * Cn];    // [b][kc][c] m_base_c partials
__device__ __align__(128) float d_Sp[Bn * 9 * OSn];   // [b][ks][j] Ws-einsum partials (ks=8: bias)
__device__ __align__(128) float d_MBp[Bn * 8 * OSn];  // [b][kc][j] m_base_s partials

// ---------------- K1: fused stats pass (half-batch per launch) ----------------
// grid (8 tiles of 512 positions, 16 b), 256 threads (8 warps).
__global__ void k1_stats(const float* __restrict__ x, int b0) {
    const int b    = blockIdx.y + b0;
    const int tile = blockIdx.x;
    const int t    = threadIdx.x;
    const int warp = t >> 5, lane = t & 31;
    const int pos0 = tile * 512;

    __shared__ float avp[8][512];
    __shared__ float mxp[8][512];

    const float4* xb = (const float4*)(x + (size_t)b * Cn * HWn);
    const int p4base = (pos0 >> 2) + lane;

    float4 av0 = {0,0,0,0}, av1 = {0,0,0,0}, av2 = {0,0,0,0}, av3 = {0,0,0,0};
    const float NI = -3.402823466e38f;
    float4 mx0 = {NI,NI,NI,NI}, mx1 = mx0, mx2 = mx0, mx3 = mx0;

    const int cbase = warp * 32;
    #pragma unroll 2
    for (int cc = 0; cc < 32; cc++) {
        const int c = cbase + cc;
        const size_t row = (size_t)c * (HWn / 4) + p4base;
        float4 v0 = __ldg(&xb[row]);
        float4 v1 = __ldg(&xb[row + 32]);
        float4 v2 = __ldg(&xb[row + 64]);
        float4 v3 = __ldg(&xb[row + 96]);

        av0.x += v0.x; av0.y += v0.y; av0.z += v0.z; av0.w += v0.w;
        av1.x += v1.x; av1.y += v1.y; av1.z += v1.z; av1.w += v1.w;
        av2.x += v2.x; av2.y += v2.y; av2.z += v2.z; av2.w += v2.w;
        av3.x += v3.x; av3.y += v3.y; av3.z += v3.z; av3.w += v3.w;
        mx0.x = fmaxf(mx0.x, v0.x); mx0.y = fmaxf(mx0.y, v0.y); mx0.z = fmaxf(mx0.z, v0.z); mx0.w = fmaxf(mx0.w, v0.w);
        mx1.x = fmaxf(mx1.x, v1.x); mx1.y = fmaxf(mx1.y, v1.y); mx1.z = fmaxf(mx1.z, v1.z); mx1.w = fmaxf(mx1.w, v1.w);
        mx2.x = fmaxf(mx2.x, v2.x); mx2.y = fmaxf(mx2.y, v2.y); mx2.z = fmaxf(mx2.z, v2.z); mx2.w = fmaxf(mx2.w, v2.w);
        mx3.x = fmaxf(mx3.x, v3.x); mx3.y = fmaxf(mx3.y, v3.y); mx3.z = fmaxf(mx3.z, v3.z); mx3.w = fmaxf(mx3.w, v3.w);

        float r = ((v0.x + v0.y) + (v0.z + v0.w)) + ((v1.x + v1.y) + (v1.z + v1.w))
                + ((v2.x + v2.y) + (v2.z + v2.w)) + ((v3.x + v3.y) + (v3.z + v3.w));
        #pragma unroll
        for (int o = 16; o; o >>= 1) r += __shfl_xor_sync(0xffffffffu, r, o);
        if (lane == 0) d_gpart[(b * 8 + tile) * Cn + c] = r;
    }

    *(float4*)&avp[warp][lane * 4]       = av0;
    *(float4*)&avp[warp][128 + lane * 4] = av1;
    *(float4*)&avp[warp][256 + lane * 4] = av2;
    *(float4*)&avp[warp][384 + lane * 4] = av3;
    *(float4*)&mxp[warp][lane * 4]       = mx0;
    *(float4*)&mxp[warp][128 + lane * 4] = mx1;
    *(float4*)&mxp[warp][256 + lane * 4] = mx2;
    *(float4*)&mxp[warp][384 + lane * 4] = mx3;
    __syncthreads();

    #pragma unroll
    for (int p = t; p < 512; p += 256) {
        float s = 0.f, m = NI;
        #pragma unroll
        for (int w = 0; w < 8; w++) { s += avp[w][p]; m = fmaxf(m, mxp[w][p]); }
        d_av[b * HWn + pos0 + p] = s * (1.f / (float)Cn);
        d_mx[b * HWn + pos0 + p] = m;
    }
}

// ---------------- K2: slim per-batch head: g, h, phi_c, phi_s ----------------
// phi dots computed by ALL 256 threads: 8-way k-split, 32 outputs each, smem reduce.
__global__ void k2_mlp(const float* __restrict__ a,
                       const float* __restrict__ W_pre, const float* __restrict__ b_pre,
                       const float* __restrict__ W_pc,  const float* __restrict__ b_pc,
                       const float* __restrict__ W_ps,  const float* __restrict__ b_ps) {
    const int b = blockIdx.x;
    const int t = threadIdx.x;
    const int j  = t & 31;      // output index within first 32 cols
    const int ks = t >> 5;      // k-chunk (8 chunks of 32)

    __shared__ float in_s[Cn + AUXn];
    __shared__ float h_s[HIDn];
    __shared__ float pcred[8][32];
    __shared__ float psred[8][32];

    {
        float g = 0.f;
        #pragma unroll
        for (int tl = 0; tl < 8; tl++) g += d_gpart[(b * 8 + tl) * Cn + t];
        in_s[t] = g * (1.f / (float)HWn);
        if (t < AUXn) in_s[Cn + t] = __ldg(a + b * AUXn + t);
    }
    __syncthreads();

    // h = relu(in @ W_pre + b_pre), dual accumulators
    {
        float a0 = __ldg(b_pre + t), a1 = 0.f;
        #pragma unroll 4
        for (int i = 0; i < Cn + AUXn; i += 2) {
            a0 = fmaf(in_s[i],     __ldg(W_pre + i * HIDn + t), a0);
            a1 = fmaf(in_s[i + 1], __ldg(W_pre + (i + 1) * HIDn + t), a1);
        }
        float h = fmaxf(a0 + a1, 0.f);
        h_s[t] = h;
        d_h[b * HIDn + t] = h;
    }
    __syncthreads();

    // phi projections: only first 32 columns of W_pc/W_ps are used by _fourier.
    {
        float pc = (ks == 0) ? __ldg(b_pc + j) : 0.f;
        float ps = (ks == 0) ? __ldg(b_ps + j) : 0.f;
        const int k0 = ks * 32;
        #pragma unroll 4
        for (int k = 0; k < 32; k++) {
            float hk = h_s[k0 + k];
            pc = fmaf(hk, __ldg(W_pc + (k0 + k) * RANKn + j), pc);
            ps = fmaf(hk, __ldg(W_ps + (k0 + k) * RANKn + j), ps);
        }
        pcred[ks][j] = pc;
        psred[ks][j] = ps;
    }
    __syncthreads();

    if (t < 32) {
        float p = 0.f;
        #pragma unroll
        for (int kk = 0; kk < 8; kk++) p += pcred[kk][t];
        float w = 1.f + (PI_F - 1.f) * (float)t / 31.f;
        float u = p * w;
        d_phic[b * RANKn + t]      = sinf(u);
        d_phic[b * RANKn + t + 32] = cosf(u);
    } else if (t < 64) {
        int r = t - 32;
        float p = 0.f;
        #pragma unroll
        for (int kk = 0; kk < 8; kk++) p += psred[kk][r];
        float w = 1.f + (PI_F - 1.f) * (float)r / 31.f;
        float u = p * w;
        d_phis[b * RANKn + r]      = sinf(u);
        d_phis[b * RANKn + r + 32] = cosf(u);
    }
}

// ---------------- K3: broadcast contractions (Wc, bias, W_bc; plus Ws/W_bs tile) ----------------
// grid (33 c-tiles, 17 splits), 256 threads. lane = b, warp = output within tile.
// ct < 32: outputs are channels c. ct == 32: outputs are the 8 spatial slots j.
__global__ void k3_einsum(const float* __restrict__ W_Wc, const float* __restrict__ b_Wc,
                          const float* __restrict__ W_bc,
                          const float* __restrict__ W_Ws, const float* __restrict__ b_Ws,
                          const float* __restrict__ W_bs) {
    const int ct = blockIdx.x;
    const int ks = blockIdx.y;
    const int t  = threadIdx.x;
    const int lane = t & 31;     // = b
    const int warp = t >> 5;
    const bool small = (ct == 32);

    __shared__ float h_s[32 * 33];
    __shared__ float phi_s[32 * 68];

    if (ks != 8) {
        const int kc = (ks < 8) ? ks : (ks - 9);
        for (int i = t; i < 32 * 32; i += 256) {
            int bb = i >> 5, kk = i & 31;
            h_s[bb * 33 + kk] = d_h[bb * HIDn + kc * 32 + kk];
        }
    }
    if (ks <= 8) {
        const float* phisrc = small ? d_phis : d_phic;
        for (int i = t; i < 32 * 64; i += 256) {
            int bb = i >> 6, r = i & 63;
            phi_s[bb * 68 + r] = phisrc[bb * RANKn + r];
        }
    }
    __syncthreads();

    if (!small) {
        const int c = ct * 8 + warp;
        if (ks < 8) {
            float acc = 0.f;
            const float* Wbase = W_Wc + (size_t)(ks * 32) * (Cn * RANKn) + c * RANKn;
            #pragma unroll 2
            for (int kk = 0; kk < 32; kk++) {
                float hk = h_s[lane * 33 + kk];
                const float4* w4 = (const float4*)(Wbase + (size_t)kk * (Cn * RANKn));
                float dot = 0.f;
                #pragma unroll
                for (int r4 = 0; r4 < 16; r4++) {
                    float4 w = __ldg(&w4[r4]);
                    float4 p = *(const float4*)(phi_s + lane * 68 + r4 * 4);
                    dot = fmaf(w.x, p.x, dot);
                    dot = fmaf(w.y, p.y, dot);
                    dot = fmaf(w.z, p.z, dot);
                    dot = fmaf(w.w, p.w, dot);
                }
                acc = fmaf(hk, dot, acc);
            }
            d_Ep[(lane * 9 + ks) * Cn + c] = acc;
        } else if (ks == 8) {
            float acc = 0.f;
            const float4* bw4 = (const float4*)(b_Wc + c * RANKn);
            #pragma unroll
            for (int r4 = 0; r4 < 16; r4++) {
                float4 w = __ldg(&bw4[r4]);
                float4 p = *(const float4*)(phi_s + lane * 68 + r4 * 4);
                acc = fmaf(w.x, p.x, acc);
                acc = fmaf(w.y, p.y, acc);
                acc = fmaf(w.z, p.z, acc);
                acc = fmaf(w.w, p.w, acc);
            }
            d_Ep[(lane * 9 + 8) * Cn + c] = acc;
        } else {
            const int kc = ks - 9;
            float a0 = 0.f, a1 = 0.f;
            const float* Wb = W_bc + (size_t)(kc * 32) * Cn + c;
            #pragma unroll 4
            for (int kk = 0; kk < 32; kk += 2) {
                a0 = fmaf(h_s[lane * 33 + kk],     __ldg(Wb + (size_t)kk * Cn), a0);
                a1 = fmaf(h_s[lane * 33 + kk + 1], __ldg(Wb + (size_t)(kk + 1) * Cn), a1);
            }
            d_Mp[(lane * 8 + kc) * Cn + c] = a0 + a1;
        }
    } else {
        const int j = warp;  // 8 warps = 8 outputs
        if (ks < 8) {
            float acc = 0.f;
            const float* Wbase = W_Ws + (size_t)(ks * 32) * (OSn * RANKn) + j * RANKn;
            #pragma unroll 2
            for (int kk = 0; kk < 32; kk++) {
                float hk = h_s[lane * 33 + kk];
                const float4* w4 = (const float4*)(Wbase + (size_t)kk * (OSn * RANKn));
                float dot = 0.f;
                #pragma unroll
                for (int r4 = 0; r4 < 16; r4++) {
                    float4 w = __ldg(&w4[r4]);
                    float4 p = *(const float4*)(phi_s + lane * 68 + r4 * 4);
                    dot = fmaf(w.x, p.x, dot);
                    dot = fmaf(w.y, p.y, dot);
                    dot = fmaf(w.z, p.z, dot);
                    dot = fmaf(w.w, p.w, dot);
                }
                acc = fmaf(hk, dot, acc);
            }
            d_Sp[(lane * 9 + ks) * OSn + j] = acc;
        } else if (ks == 8) {
            float acc = 0.f;
            const float4* bw4 = (const float4*)(b_Ws + j * RANKn);
            #pragma unroll
            for (int r4 = 0; r4 < 16; r4++) {
                float4 w = __ldg(&bw4[r4]);
                float4 p = *(const float4*)(phi_s + lane * 68 + r4 * 4);
                acc = fmaf(w.x, p.x, acc);
                acc = fmaf(w.y, p.y, acc);
                acc = fmaf(w.z, p.z, acc);
                acc = fmaf(w.w, p.w, acc);
            }
            d_Sp[(lane * 9 + 8) * OSn + j] = acc;
        } else {
            const int kc = ks - 9;
            float a0 = 0.f;
            const float* Wb = W_bs + (size_t)(kc * 32) * OSn + j;
            #pragma unroll 4
            for (int kk = 0; kk < 32; kk++)
                a0 = fmaf(h_s[lane * 33 + kk], __ldg(Wb + (size_t)kk * OSn), a0);
            d_MBp[(lane * 8 + kc) * OSn + j] = a0;
        }
    }
}

// ---------------- K5: fused sig tables + s_m/pco reconstruction + output pass ----------------
__global__ void k5_out(const float* __restrict__ x, float* __restrict__ out,
                       const float* __restrict__ b_bc, const float* __restrict__ b_bs) {
    const int t   = threadIdx.x;
    const int hw4 = blockIdx.x * 256 + t;
    const int bcg = blockIdx.y;
    const int b   = bcg >> 3;
    const int cg  = bcg & 7;

    __shared__ float sig_s[32];
    __shared__ float sm_s[OSn];
    __shared__ float pc_s[10];

    if (t < 32) {
        const int c = cg * 32 + t;
        float e = 0.f;
        #pragma unroll
        for (int ks = 0; ks < 9; ks++) e += d_Ep[(b * 9 + ks) * Cn + c];
        float m = __ldg(b_bc + c);
        #pragma unroll
        for (int kc = 0; kc < 8; kc++) m += d_Mp[(b * 8 + kc) * Cn + c];
        float cm = m * e;
        sig_s[t] = 1.f / (1.f + expf(-cm));
    } else if (t < 40) {
        const int j = t - 32;
        float e = 0.f;
        #pragma unroll
        for (int ks = 0; ks < 9; ks++) e += d_Sp[(b * 9 + ks) * OSn + j];
        float m = __ldg(b_bs + j);
        #pragma unroll
        for (int kc = 0; kc < 8; kc++) m += d_MBp[(b * 8 + kc) * OSn + j];
        sm_s[j] = m * e;
    }
    __syncthreads();

    if (t < 8) {
        pc_s[(t >> 2) * 5 + (t & 3)] = sm_s[t];
    } else if (t < 10) {
        int jj = t - 8;
        pc_s[jj * 5 + 4] = -(sm_s[jj * 4] + sm_s[jj * 4 + 1] + sm_s[jj * 4 + 2] + sm_s[jj * 4 + 3]);
    }
    __syncthreads();

    // convsig for this thread's 4 positions (recompute; L2-resident av/mx)
    const float* av = d_av + b * HWn;
    const float* mx = d_mx + b * HWn;
    float cvr[4];
    #pragma unroll
    for (int j = 0; j < 4; j++) {
        const int p  = hw4 * 4 + j;
        const int hh = p >> 6, ww = p & 63;
        float up_a = (hh > 0)      ? __ldg(av + p - Wn) : 0.f;
        float dn_a = (hh < Hn - 1) ? __ldg(av + p + Wn) : 0.f;
        float lf_a = (ww > 0)      ? __ldg(av + p - 1)  : 0.f;
        float rt_a = (ww < Wn - 1) ? __ldg(av + p + 1)  : 0.f;
        float ce_a = __ldg(av + p);
        float up_m = (hh > 0)      ? __ldg(mx + p - Wn) : 0.f;
        float dn_m = (hh < Hn - 1) ? __ldg(mx + p + Wn) : 0.f;
        float lf_m = (ww > 0)      ? __ldg(mx + p - 1)  : 0.f;
        float rt_m = (ww < Wn - 1) ? __ldg(mx + p + 1)  : 0.f;
        float ce_m = __ldg(mx + p);
        float conv = pc_s[0] * up_a + pc_s[1] * dn_a + pc_s[2] * lf_a + pc_s[3] * rt_a + pc_s[4] * ce_a
                   + pc_s[5] * up_m + pc_s[6] * dn_m + pc_s[7] * lf_m + pc_s[8] * rt_m + pc_s[9] * ce_m;
        cvr[j] = 1.f / (1.f + expf(-conv));
    }

    const size_t base = ((size_t)(b * Cn + cg * 32)) * (HWn / 4) + hw4;
    const float4* x4 = (const float4*)x;
    float4* o4 = (float4*)out;

    #pragma unroll 8
    for (int ci = 0; ci < 32; ci++) {
        float s = sig_s[ci] + 1.f;
        float4 v = __ldg(&x4[base + (size_t)ci * (HWn / 4)]);
        float4 o;
        o.x = v.x * (s + cvr[0]);
        o.y = v.y * (s + cvr[1]);
        o.z = v.z * (s + cvr[2]);
        o.w = v.w * (s + cvr[3]);
        o4[base + (size_t)ci * (HWn / 4)] = o;
    }
}

// ---------------- launch ----------------
extern "C" void kernel_launch(void* const* d_in, const int* in_sizes, int n_in,
                              void* d_out, int out_size) {
    (void)in_sizes; (void)n_in; (void)out_size;
    const float* x     = (const float*)d_in[0];
    const float* a     = (const float*)d_in[1];
    const float* W_pre = (const float*)d_in[2];
    const float* b_pre = (const float*)d_in[3];
    const float* W_bc  = (const float*)d_in[4];
    const float* b_bc  = (const float*)d_in[5];
    const float* W_bs  = (const float*)d_in[6];
    const float* b_bs  = (const float*)d_in[7];
    const float* W_pc  = (const float*)d_in[8];
    const float* b_pc  = (const float*)d_in[9];
    const float* W_ps  = (const float*)d_in[10];
    const float* b_ps  = (const float*)d_in[11];
    const float* W_Wc  = (const float*)d_in[12];
    const float* b_Wc  = (const float*)d_in[13];
    const float* W_Ws  = (const float*)d_in[14];
    const float* b_Ws  = (const float*)d_in[15];
    float* out = (float*)d_out;

    k1_stats <<<dim3(8, 16), 256>>>(x, 0);    // launch 0
    k1_stats <<<dim3(8, 16), 256>>>(x, 16);   // launch 1
    k2_mlp   <<<Bn, 256>>>(a, W_pre, b_pre, W_pc, b_pc, W_ps, b_ps);   // launch 2
    k3_einsum<<<dim3(33, 17), 256>>>(W_Wc, b_Wc, W_bc, W_Ws, b_Ws, W_bs); // launch 3 (profiled)
    k5_out   <<<dim3(4, Bn * 8), 256>>>(x, out, b_bc, b_bs);           // launch 4
}

// round 7
// speedup vs baseline: 1.7251x; 1.1468x over previous
#include <cuda_runtime.h>
#include <math.h>

#define Bn   32
#define Cn   256
#define Hn   64
#define Wn   64
#define HWn  4096
#define AUXn 64
#define RANKn 64
#define HIDn 256
#define OSn  8
#define PI_F 3.14159265358979323846f

// ---------------- scratch ----------------
__device__ __align__(128) float d_gpart[Bn * 16 * Cn];
__device__ __align__(128) float d_av[Bn * HWn];
__device__ __align__(128) float d_mx[Bn * HWn];
__device__ __align__(128) float d_h[Bn * HIDn];
__device__ __align__(128) float d_phic[Bn * RANKn];
__device__ __align__(128) float d_phis[Bn * RANKn];
__device__ __align__(128) float d_Ep[Bn * 33 * Cn];   // [b][kt(32)+bias(1)][c]
__device__ __align__(128) float d_Mp[Bn * 8 * Cn];    // [b][kc][c] m_base_c partials
__device__ __align__(128) float d_Sp[Bn * 9 * OSn];   // [b][ks][j] Ws partials (ks=8: bias)
__device__ __align__(128) float d_MBp[Bn * 8 * OSn];  // [b][kc][j] m_base_s partials

// ---------------- K1: stats pass, shfl-free hot loop ----------------
// grid (16 tiles of 256 positions, 32 b), 256 threads (8 warps).
// Warp w owns channels [w*32, w*32+32); lane covers 256 positions as 2x LDG.128.
__global__ void k1_stats(const float* __restrict__ x) {
    const int b    = blockIdx.y;
    const int tile = blockIdx.x;
    const int t    = threadIdx.x;
    const int warp = t >> 5, lane = t & 31;
    const int pos0 = tile * 256;

    __shared__ float avp[8][256];        // 8 KB
    __shared__ float mxp[8][256];        // 8 KB
    __shared__ float rs[Cn * 17];        // 17.4 KB rowsum halves [c][lane<16]

    const float4* xb = (const float4*)(x + (size_t)b * Cn * HWn);
    const int p4base = (pos0 >> 2) + lane;

    float4 av0 = {0,0,0,0}, av1 = {0,0,0,0};
    const float NI = -3.402823466e38f;
    float4 mx0 = {NI,NI,NI,NI}, mx1 = mx0;

    const int cbase = warp * 32;
    #pragma unroll 4
    for (int cc = 0; cc < 32; cc++) {
        const int c = cbase + cc;
        const size_t row = (size_t)c * (HWn / 4) + p4base;
        float4 v0 = __ldg(&xb[row]);
        float4 v1 = __ldg(&xb[row + 32]);

        av0.x += v0.x; av0.y += v0.y; av0.z += v0.z; av0.w += v0.w;
        av1.x += v1.x; av1.y += v1.y; av1.z += v1.z; av1.w += v1.w;
        mx0.x = fmaxf(mx0.x, v0.x); mx0.y = fmaxf(mx0.y, v0.y); mx0.z = fmaxf(mx0.z, v0.z); mx0.w = fmaxf(mx0.w, v0.w);
        mx1.x = fmaxf(mx1.x, v1.x); mx1.y = fmaxf(mx1.y, v1.y); mx1.z = fmaxf(mx1.z, v1.z); mx1.w = fmaxf(mx1.w, v1.w);

        float r = ((v0.x + v0.y) + (v0.z + v0.w)) + ((v1.x + v1.y) + (v1.z + v1.w));
        r += __shfl_xor_sync(0xffffffffu, r, 16);       // single shfl: pair-reduce
        if (lane < 16) rs[c * 17 + lane] = r;
    }

    *(float4*)&avp[warp][lane * 4]       = av0;
    *(float4*)&avp[warp][128 + lane * 4] = av1;
    *(float4*)&mxp[warp][lane * 4]       = mx0;
    *(float4*)&mxp[warp][128 + lane * 4] = mx1;
    __syncthreads();

    {   // av / mx finalize: t = local position
        float s = 0.f, m = NI;
        #pragma unroll
        for (int w = 0; w < 8; w++) { s += avp[w][t]; m = fmaxf(m, mxp[w][t]); }
        d_av[b * HWn + pos0 + t] = s * (1.f / (float)Cn);
        d_mx[b * HWn + pos0 + t] = m;
    }
    {   // gpart: t = channel, sum 16 halves
        float g = 0.f;
        #pragma unroll
        for (int l = 0; l < 16; l++) g += rs[t * 17 + l];
        d_gpart[(b * 16 + tile) * Cn + t] = g;
    }
}

// ---------------- K2: slim per-batch head: g, h, phi_c, phi_s ----------------
__global__ void k2_mlp(const float* __restrict__ a,
                       const float* __restrict__ W_pre, const float* __restrict__ b_pre,
                       const float* __restrict__ W_pc,  const float* __restrict__ b_pc,
                       const float* __restrict__ W_ps,  const float* __restrict__ b_ps) {
    const int b = blockIdx.x;
    const int t = threadIdx.x;
    const int j  = t & 31;
    const int ks = t >> 5;

    __shared__ float in_s[Cn + AUXn];
    __shared__ float h_s[HIDn];
    __shared__ float pcred[8][32];
    __shared__ float psred[8][32];

    {
        float g = 0.f;
        #pragma unroll
        for (int tl = 0; tl < 16; tl++) g += d_gpart[(b * 16 + tl) * Cn + t];
        in_s[t] = g * (1.f / (float)HWn);
        if (t < AUXn) in_s[Cn + t] = __ldg(a + b * AUXn + t);
    }
    __syncthreads();

    {
        float a0 = __ldg(b_pre + t), a1 = 0.f;
        #pragma unroll 4
        for (int i = 0; i < Cn + AUXn; i += 2) {
            a0 = fmaf(in_s[i],     __ldg(W_pre + i * HIDn + t), a0);
            a1 = fmaf(in_s[i + 1], __ldg(W_pre + (i + 1) * HIDn + t), a1);
        }
        float h = fmaxf(a0 + a1, 0.f);
        h_s[t] = h;
        d_h[b * HIDn + t] = h;
    }
    __syncthreads();

    {
        float pc = (ks == 0) ? __ldg(b_pc + j) : 0.f;
        float ps = (ks == 0) ? __ldg(b_ps + j) : 0.f;
        const int k0 = ks * 32;
        #pragma unroll 4
        for (int k = 0; k < 32; k++) {
            float hk = h_s[k0 + k];
            pc = fmaf(hk, __ldg(W_pc + (k0 + k) * RANKn + j), pc);
            ps = fmaf(hk, __ldg(W_ps + (k0 + k) * RANKn + j), ps);
        }
        pcred[ks][j] = pc;
        psred[ks][j] = ps;
    }
    __syncthreads();

    if (t < 32) {
        float p = 0.f;
        #pragma unroll
        for (int kk = 0; kk < 8; kk++) p += pcred[kk][t];
        float w = 1.f + (PI_F - 1.f) * (float)t / 31.f;
        float u = p * w;
        d_phic[b * RANKn + t]      = sinf(u);
        d_phic[b * RANKn + t + 32] = cosf(u);
    } else if (t < 64) {
        int r = t - 32;
        float p = 0.f;
        #pragma unroll
        for (int kk = 0; kk < 8; kk++) p += psred[kk][r];
        float w = 1.f + (PI_F - 1.f) * (float)r / 31.f;
        float u = p * w;
        d_phis[b * RANKn + r]      = sinf(u);
        d_phis[b * RANKn + r + 32] = cosf(u);
    }
}

// ---------------- K3: smem-staged GEMM for Wc einsum + small contractions ----------------
// 1D grid of 817 blocks, 256 threads:
//   blk <  512 : GEMM tile — kt = blk>>4 (8 k's), ct = blk&15 (16 c's). W staged in smem.
//   512..767   : Mp (W_bc) — ct8 = q&31 (8 c's), kc = q>>5 (32 k's), broadcast ldg.
//   768..799   : Ep bias (b_Wc) — ct8 = blk-768.
//   800..816   : Ws/W_bs/b_Ws small tile — role ks = blk-800 (as before).
__global__ void __launch_bounds__(256) k3_einsum(
        const float* __restrict__ W_Wc, const float* __restrict__ b_Wc,
        const float* __restrict__ W_bc,
        const float* __restrict__ W_Ws, const float* __restrict__ b_Ws,
        const float* __restrict__ W_bs) {
    const int blk = blockIdx.x;
    const int t   = threadIdx.x;
    const int lane = t & 31;     // = b
    const int warp = t >> 5;

    __shared__ float Wt[8 * 1024];       // 32 KB GEMM tile
    __shared__ float h_s[32 * 33];       // [b][kk] padded (33 odd -> conflict-free)
    __shared__ float phi_s[32 * 68];     // [b][r]  padded (LDS.128 conflict-free)

    if (blk < 512) {
        // ---------- GEMM path ----------
        const int kt = blk >> 4;
        const int ct = blk & 15;

        const float4* Wg = (const float4*)(W_Wc + (size_t)(kt * 8) * (Cn * RANKn) + ct * 1024);
        #pragma unroll
        for (int i = t; i < 2048; i += 256) {
            int kk = i >> 8, jj = i & 255;
            ((float4*)Wt)[i] = __ldg(&Wg[(size_t)kk * 4096 + jj]);
        }
        if (t < 256) {   // 32b x 8k
            int bb = t >> 3, kk = t & 7;
            h_s[bb * 33 + kk] = d_h[bb * HIDn + kt * 8 + kk];
        }
        for (int i = t; i < 2048; i += 256) {
            int bb = i >> 6, r = i & 63;
            phi_s[bb * 68 + r] = d_phic[bb * RANKn + r];
        }
        __syncthreads();

        float4 ph[16];
        #pragma unroll
        for (int i = 0; i < 16; i++) ph[i] = *(const float4*)(phi_s + lane * 68 + i * 4);

        #pragma unroll
        for (int cj = 0; cj < 2; cj++) {
            const int cl = warp * 2 + cj;
            float acc = 0.f;
            #pragma unroll
            for (int kk = 0; kk < 8; kk++) {
                const float4* w4 = (const float4*)(Wt + kk * 1024 + cl * 64);
                float d0 = 0.f, d1 = 0.f;
                #pragma unroll
                for (int q = 0; q < 16; q += 2) {
                    float4 wa = w4[q], wb = w4[q + 1];
                    d0 = fmaf(wa.x, ph[q].x, d0);
                    d0 = fmaf(wa.y, ph[q].y, d0);
                    d0 = fmaf(wa.z, ph[q].z, d0);
                    d0 = fmaf(wa.w, ph[q].w, d0);
                    d1 = fmaf(wb.x, ph[q + 1].x, d1);
                    d1 = fmaf(wb.y, ph[q + 1].y, d1);
                    d1 = fmaf(wb.z, ph[q + 1].z, d1);
                    d1 = fmaf(wb.w, ph[q + 1].w, d1);
                }
                acc = fmaf(h_s[lane * 33 + kk], d0 + d1, acc);
            }
            d_Ep[(lane * 33 + kt) * Cn + ct * 16 + cl] = acc;
        }
    } else if (blk < 768) {
        // ---------- Mp (W_bc) path ----------
        const int q = blk - 512;
        const int ct8 = q & 31, kc = q >> 5;
        const int c = ct8 * 8 + warp;
        for (int i = t; i < 32 * 32; i += 256) {
            int bb = i >> 5, kk = i & 31;
            h_s[bb * 33 + kk] = d_h[bb * HIDn + kc * 32 + kk];
        }
        __syncthreads();
        float a0 = 0.f, a1 = 0.f;
        const float* Wb = W_bc + (size_t)(kc * 32) * Cn + c;
        #pragma unroll 4
        for (int kk = 0; kk < 32; kk += 2) {
            a0 = fmaf(h_s[lane * 33 + kk],     __ldg(Wb + (size_t)kk * Cn), a0);
            a1 = fmaf(h_s[lane * 33 + kk + 1], __ldg(Wb + (size_t)(kk + 1) * Cn), a1);
        }
        d_Mp[(lane * 8 + kc) * Cn + c] = a0 + a1;
    } else if (blk < 800) {
        // ---------- Ep bias (b_Wc) path ----------
        const int ct8 = blk - 768;
        const int c = ct8 * 8 + warp;
        for (int i = t; i < 32 * 64; i += 256) {
            int bb = i >> 6, r = i & 63;
            phi_s[bb * 68 + r] = d_phic[bb * RANKn + r];
        }
        __syncthreads();
        float acc = 0.f;
        const float4* bw4 = (const float4*)(b_Wc + c * RANKn);
        #pragma unroll
        for (int r4 = 0; r4 < 16; r4++) {
            float4 w = __ldg(&bw4[r4]);
            float4 p = *(const float4*)(phi_s + lane * 68 + r4 * 4);
            acc = fmaf(w.x, p.x, acc);
            acc = fmaf(w.y, p.y, acc);
            acc = fmaf(w.z, p.z, acc);
            acc = fmaf(w.w, p.w, acc);
        }
        d_Ep[(lane * 33 + 32) * Cn + c] = acc;
    } else {
        // ---------- Ws / b_Ws / W_bs small-tile path ----------
        const int ks = blk - 800;   // 0..16
        if (ks != 8) {
            const int kc = (ks < 8) ? ks : (ks - 9);
            for (int i = t; i < 32 * 32; i += 256) {
                int bb = i >> 5, kk = i & 31;
                h_s[bb * 33 + kk] = d_h[bb * HIDn + kc * 32 + kk];
            }
        }
        if (ks <= 8) {
            for (int i = t; i < 32 * 64; i += 256) {
                int bb = i >> 6, r = i & 63;
                phi_s[bb * 68 + r] = d_phis[bb * RANKn + r];
            }
        }
        __syncthreads();

        const int j = warp;
        if (ks < 8) {
            float acc = 0.f;
            const float* Wbase = W_Ws + (size_t)(ks * 32) * (OSn * RANKn) + j * RANKn;
            #pragma unroll 2
            for (int kk = 0; kk < 32; kk++) {
                float hk = h_s[lane * 33 + kk];
                const float4* w4 = (const float4*)(Wbase + (size_t)kk * (OSn * RANKn));
                float dot = 0.f;
                #pragma unroll
                for (int r4 = 0; r4 < 16; r4++) {
                    float4 w = __ldg(&w4[r4]);
                    float4 p = *(const float4*)(phi_s + lane * 68 + r4 * 4);
                    dot = fmaf(w.x, p.x, dot);
                    dot = fmaf(w.y, p.y, dot);
                    dot = fmaf(w.z, p.z, dot);
                    dot = fmaf(w.w, p.w, dot);
                }
                acc = fmaf(hk, dot, acc);
            }
            d_Sp[(lane * 9 + ks) * OSn + j] = acc;
        } else if (ks == 8) {
            float acc = 0.f;
            const float4* bw4 = (const float4*)(b_Ws + j * RANKn);
            #pragma unroll
            for (int r4 = 0; r4 < 16; r4++) {
                float4 w = __ldg(&bw4[r4]);
                float4 p = *(const float4*)(phi_s + lane * 68 + r4 * 4);
                acc = fmaf(w.x, p.x, acc);
                acc = fmaf(w.y, p.y, acc);
                acc = fmaf(w.z, p.z, acc);
                acc = fmaf(w.w, p.w, acc);
            }
            d_Sp[(lane * 9 + 8) * OSn + j] = acc;
        } else {
            const int kc = ks - 9;
            float a0 = 0.f;
            const float* Wb = W_bs + (size_t)(kc * 32) * OSn + j;
            #pragma unroll 4
            for (int kk = 0; kk < 32; kk++)
                a0 = fmaf(h_s[lane * 33 + kk], __ldg(Wb + (size_t)kk * OSn), a0);
            d_MBp[(lane * 8 + kc) * OSn + j] = a0;
        }
    }
}

// ---------------- K5: fused sig tables + stencil + output pass ----------------
__global__ void k5_out(const float* __restrict__ x, float* __restrict__ out,
                       const float* __restrict__ b_bc, const float* __restrict__ b_bs) {
    const int t   = threadIdx.x;
    const int hw4 = blockIdx.x * 256 + t;
    const int bcg = blockIdx.y;
    const int b   = bcg >> 3;
    const int cg  = bcg & 7;

    __shared__ float sig_s[32];
    __shared__ float sm_s[OSn];
    __shared__ float pc_s[10];

    if (t < 32) {
        const int c = cg * 32 + t;
        float e = 0.f;
        #pragma unroll
        for (int ks = 0; ks < 33; ks++) e += d_Ep[(b * 33 + ks) * Cn + c];
        float m = __ldg(b_bc + c);
        #pragma unroll
        for (int kc = 0; kc < 8; kc++) m += d_Mp[(b * 8 + kc) * Cn + c];
        float cm = m * e;
        sig_s[t] = 1.f / (1.f + expf(-cm));
    } else if (t < 40) {
        const int j = t - 32;
        float e = 0.f;
        #pragma unroll
        for (int ks = 0; ks < 9; ks++) e += d_Sp[(b * 9 + ks) * OSn + j];
        float m = __ldg(b_bs + j);
        #pragma unroll
        for (int kc = 0; kc < 8; kc++) m += d_MBp[(b * 8 + kc) * OSn + j];
        sm_s[j] = m * e;
    }
    __syncthreads();

    if (t < 8) {
        pc_s[(t >> 2) * 5 + (t & 3)] = sm_s[t];
    } else if (t < 10) {
        int jj = t - 8;
        pc_s[jj * 5 + 4] = -(sm_s[jj * 4] + sm_s[jj * 4 + 1] + sm_s[jj * 4 + 2] + sm_s[jj * 4 + 3]);
    }
    __syncthreads();

    const float* av = d_av + b * HWn;
    const float* mx = d_mx + b * HWn;
    float cvr[4];
    #pragma unroll
    for (int j = 0; j < 4; j++) {
        const int p  = hw4 * 4 + j;
        const int hh = p >> 6, ww = p & 63;
        float up_a = (hh > 0)      ? __ldg(av + p - Wn) : 0.f;
        float dn_a = (hh < Hn - 1) ? __ldg(av + p + Wn) : 0.f;
        float lf_a = (ww > 0)      ? __ldg(av + p - 1)  : 0.f;
        float rt_a = (ww < Wn - 1) ? __ldg(av + p + 1)  : 0.f;
        float ce_a = __ldg(av + p);
        float up_m = (hh > 0)      ? __ldg(mx + p - Wn) : 0.f;
        float dn_m = (hh < Hn - 1) ? __ldg(mx + p + Wn) : 0.f;
        float lf_m = (ww > 0)      ? __ldg(mx + p - 1)  : 0.f;
        float rt_m = (ww < Wn - 1) ? __ldg(mx + p + 1)  : 0.f;
        float ce_m = __ldg(mx + p);
        float conv = pc_s[0] * up_a + pc_s[1] * dn_a + pc_s[2] * lf_a + pc_s[3] * rt_a + pc_s[4] * ce_a
                   + pc_s[5] * up_m + pc_s[6] * dn_m + pc_s[7] * lf_m + pc_s[8] * rt_m + pc_s[9] * ce_m;
        cvr[j] = 1.f / (1.f + expf(-conv));
    }

    const size_t base = ((size_t)(b * Cn + cg * 32)) * (HWn / 4) + hw4;
    const float4* x4 = (const float4*)x;
    float4* o4 = (float4*)out;

    #pragma unroll 8
    for (int ci = 0; ci < 32; ci++) {
        float s = sig_s[ci] + 1.f;
        float4 v = __ldg(&x4[base + (size_t)ci * (HWn / 4)]);
        float4 o;
        o.x = v.x * (s + cvr[0]);
        o.y = v.y * (s + cvr[1]);
        o.z = v.z * (s + cvr[2]);
        o.w = v.w * (s + cvr[3]);
        o4[base + (size_t)ci * (HWn / 4)] = o;
    }
}

// ---------------- launch ----------------
extern "C" void kernel_launch(void* const* d_in, const int* in_sizes, int n_in,
                              void* d_out, int out_size) {
    (void)in_sizes; (void)n_in; (void)out_size;
    const float* x     = (const float*)d_in[0];
    const float* a     = (const float*)d_in[1];
    const float* W_pre = (const float*)d_in[2];
    const float* b_pre = (const float*)d_in[3];
    const float* W_bc  = (const float*)d_in[4];
    const float* b_bc  = (const float*)d_in[5];
    const float* W_bs  = (const float*)d_in[6];
    const float* b_bs  = (const float*)d_in[7];
    const float* W_pc  = (const float*)d_in[8];
    const float* b_pc  = (const float*)d_in[9];
    const float* W_ps  = (const float*)d_in[10];
    const float* b_ps  = (const float*)d_in[11];
    const float* W_Wc  = (const float*)d_in[12];
    const float* b_Wc  = (const float*)d_in[13];
    const float* W_Ws  = (const float*)d_in[14];
    const float* b_Ws  = (const float*)d_in[15];
    float* out = (float*)d_out;

    k1_stats <<<dim3(16, Bn), 256>>>(x);                              // launch 0
    k2_mlp   <<<Bn, 256>>>(a, W_pre, b_pre, W_pc, b_pc, W_ps, b_ps);  // launch 1
    k3_einsum<<<817, 256>>>(W_Wc, b_Wc, W_bc, W_Ws, b_Ws, W_bs);      // launch 2
    k5_out   <<<dim3(4, Bn * 8), 256>>>(x, out, b_bc, b_bs);          // launch 3 (profiled)
}